// round 14
// baseline (speedup 1.0000x reference)
#include <cuda_runtime.h>
#include <cuda_fp16.h>
#include <cstdint>
#include <math.h>

#define BDIM 2
#define CDIM 512
#define NSP  4096
#define GROUPS 32
#define CPG  16

// ---- static scratch ----
__device__ __half g_hnT[(size_t)BDIM * NSP * CDIM];   // [b][n][c]
__device__ __half g_qkT[(size_t)BDIM * NSP * 1024];   // [b][n][q:512|k:512]
__device__ __half g_v  [(size_t)BDIM * CDIM * NSP];   // [b][c][n]
__device__ __half g_oT [(size_t)BDIM * NSP * CDIM];   // [b][n][c]
__device__ __half g_s  [(size_t)BDIM * NSP * NSP];    // [b][i][j] exp-scores
__device__ float  g_rsp[(size_t)BDIM * NSP * 32];     // row-sum partials [row][jb]
__device__ float  g_rs [(size_t)BDIM * NSP];          // 1/rowsum
__device__ float2 g_gnp[BDIM * GROUPS * 8];           // gn partial (sum, sumsq)
__device__ float2 g_gst[BDIM * GROUPS];               // gn (mean, rstd)
__device__ __half g_wqk[1024 * CDIM];
__device__ float  g_bqk[1024];
__device__ __half g_wv [CDIM * CDIM];
__device__ __half g_wp [CDIM * CDIM];

// ---------------- reductions ----------------
__device__ __forceinline__ float blockReduceSum(float v, float* sh) {
    #pragma unroll
    for (int o = 16; o; o >>= 1) v += __shfl_down_sync(0xffffffffu, v, o);
    int lane = threadIdx.x & 31, wid = threadIdx.x >> 5;
    if (lane == 0) sh[wid] = v;
    __syncthreads();
    int nw = blockDim.x >> 5;
    v = (threadIdx.x < nw) ? sh[threadIdx.x] : 0.f;
    if (wid == 0) {
        #pragma unroll
        for (int o = 16; o; o >>= 1) v += __shfl_down_sync(0xffffffffu, v, o);
    }
    return v;
}

// ---------------- weights fp32->fp16 (+ q|k concat) ----------------
__global__ void __launch_bounds__(256)
w2h(const float* __restrict__ wq, const float* __restrict__ wk,
    const float* __restrict__ wv, const float* __restrict__ wp,
    const float* __restrict__ bq, const float* __restrict__ bk,
    __half* __restrict__ Wqk, __half* __restrict__ Wv,
    __half* __restrict__ Wp, float* __restrict__ Bqk) {
    int i = blockIdx.x * 256 + threadIdx.x;
    if (i < CDIM * CDIM) {
        Wqk[i] = __float2half_rn(wq[i]);
        Wqk[i + CDIM * CDIM] = __float2half_rn(wk[i]);
        Wv[i] = __float2half_rn(wv[i]);
        Wp[i] = __float2half_rn(wp[i]);
    }
    if (i < CDIM) { Bqk[i] = bq[i]; Bqk[i + CDIM] = bk[i]; }
}

// ---------------- GroupNorm pass 1: partial sums ----------------
__global__ void __launch_bounds__(256)
gn_stats1(const float* __restrict__ x, float2* __restrict__ gnp) {
    __shared__ float sh[32];
    int blk = blockIdx.x;
    int chunk = blk & 7, bg = blk >> 3;
    const float* xp = x + (size_t)bg * CPG * NSP + chunk * 512;
    const float4* xp4 = reinterpret_cast<const float4*>(xp);
    int t = threadIdx.x;
    float s = 0.f, ss = 0.f;
    for (int i = t; i < 2048; i += 256) {
        int c = i >> 7, n4 = i & 127;
        float4 v = xp4[c * (NSP / 4) + n4];
        s  += v.x + v.y + v.z + v.w;
        ss += v.x * v.x + v.y * v.y + v.z * v.z + v.w * v.w;
    }
    float ts = blockReduceSum(s, sh);
    __syncthreads();
    float tss = blockReduceSum(ss, sh);
    if (t == 0) gnp[blk] = make_float2(ts, tss);
}

// ---------------- GroupNorm pass 2: reduce to (mean, rstd) ----------------
__global__ void __launch_bounds__(32)
gn_stats2(const float2* __restrict__ gnp, float2* __restrict__ gst) {
    int lane = threadIdx.x;
    float s = 0.f, ss = 0.f;
    if (lane < 8) {
        float2 p = gnp[blockIdx.x * 8 + lane];
        s = p.x; ss = p.y;
    }
    #pragma unroll
    for (int o = 4; o; o >>= 1) {
        s  += __shfl_down_sync(0xffffffffu, s, o);
        ss += __shfl_down_sync(0xffffffffu, ss, o);
    }
    if (lane == 0) {
        float mean = s / 65536.f;
        float var  = ss / 65536.f - mean * mean;
        gst[blockIdx.x] = make_float2(mean, rsqrtf(var + 1e-6f));
    }
}

// ---------------- GroupNorm pass 3: normalize + transpose ----------------
__global__ void __launch_bounds__(256)
gn_norm(const float* __restrict__ x, const float* __restrict__ w,
        const float* __restrict__ bb, const float2* __restrict__ gst,
        __half* __restrict__ hnT) {
    __shared__ float tile[16][129];
    int blk = blockIdx.x;
    int chunk = blk & 7, bg = blk >> 3;
    int b = bg / GROUPS, g = bg % GROUPS;
    const float* xp = x + (size_t)bg * CPG * NSP;
    float2 st = gst[bg];
    float mean = st.x, rstd = st.y;
    int t = threadIdx.x;

    __half* hT = hnT + (size_t)b * NSP * CDIM;

    for (int sub = 0; sub < 4; sub++) {
        int n0 = chunk * 512 + sub * 128;
        #pragma unroll
        for (int e = 0; e < 8; e++) {
            int idx = e * 256 + t;
            int c = idx >> 7, n = idx & 127;
            float v = xp[(size_t)c * NSP + n0 + n];
            tile[c][n] = (v - mean) * rstd * w[g * CPG + c] + bb[g * CPG + c];
        }
        __syncthreads();
        int n = t >> 1, ch = (t & 1) * 8;
        __half2 h0 = __floats2half2_rn(tile[ch + 0][n], tile[ch + 1][n]);
        __half2 h1 = __floats2half2_rn(tile[ch + 2][n], tile[ch + 3][n]);
        __half2 h2 = __floats2half2_rn(tile[ch + 4][n], tile[ch + 5][n]);
        __half2 h3 = __floats2half2_rn(tile[ch + 6][n], tile[ch + 7][n]);
        uint4 pk;
        pk.x = *reinterpret_cast<uint32_t*>(&h0);
        pk.y = *reinterpret_cast<uint32_t*>(&h1);
        pk.z = *reinterpret_cast<uint32_t*>(&h2);
        pk.w = *reinterpret_cast<uint32_t*>(&h3);
        *reinterpret_cast<uint4*>(&hT[(size_t)(n0 + n) * CDIM + g * CPG + ch]) = pk;
        __syncthreads();
    }
}

// ---------------- fp16 tensor-core GEMM, 256thr / 128x128 / BK=64 / 3-stage ----------------
__device__ __forceinline__ void mma_f16(float* c, const uint32_t* a, const uint32_t* b) {
    asm volatile(
        "mma.sync.aligned.m16n8k16.row.col.f32.f16.f16.f32 "
        "{%0,%1,%2,%3}, {%4,%5,%6,%7}, {%8,%9}, {%0,%1,%2,%3};"
        : "+f"(c[0]), "+f"(c[1]), "+f"(c[2]), "+f"(c[3])
        : "r"(a[0]), "r"(a[1]), "r"(a[2]), "r"(a[3]), "r"(b[0]), "r"(b[1]));
}
__device__ __forceinline__ void ldmx4(uint32_t* r, uint32_t addr) {
    asm volatile("ldmatrix.sync.aligned.m8n8.x4.shared.b16 {%0,%1,%2,%3}, [%4];"
                 : "=r"(r[0]), "=r"(r[1]), "=r"(r[2]), "=r"(r[3]) : "r"(addr));
}
__device__ __forceinline__ void cpasync16(uint32_t dst, const void* src) {
    asm volatile("cp.async.cg.shared.global [%0], [%1], 16;\n" :: "r"(dst), "l"(src));
}
__device__ __forceinline__ void cp_commit() {
    asm volatile("cp.async.commit_group;\n" ::: "memory");
}

// D[m][n] = sum_k A[m][k]*B[n][k]  (fp16, K-contiguous rows)
// EPI: 0:+aux[n] fp16  1:+aux[m] fp16  2:exp(v*scale)+rowsum partials fp16
//      3:*aux[bz*NSP+m] fp16  4:+aux[m]+resid fp32
#define BM 128
#define BN 128
#define BK 64
#define RSTR 144
#define ATSZ (128 * RSTR)        // 18432
#define BTSZ (128 * RSTR)        // 18432
#define STGB (ATSZ + BTSZ)       // 36864
#define NSTAGE 3

template<int EPI>
__global__ void __launch_bounds__(256, 2)
gemm_h(const __half* __restrict__ A, const __half* __restrict__ B, void* __restrict__ Cv,
       int K, int lda, int ldb, int ldc, size_t sA, size_t sB, size_t sC,
       const float* __restrict__ aux, const float* __restrict__ resid,
       float* __restrict__ rsp, float scale) {
    extern __shared__ char dsm[];
    __shared__ float sm_rs[4][BM];
    int bz = blockIdx.z;
    A += sA * (size_t)bz;
    B += sB * (size_t)bz;

    const int m0 = blockIdx.y * BM;
    const int n0 = blockIdx.x * BN;
    int t = threadIdx.x, wid = t >> 5, lane = t & 31;
    int wm = wid >> 2, wn = wid & 3;     // 2 x 4 warps; warp tile 64x32
    int gr = lane >> 2, gc = lane & 3;

    uint32_t sbase = ((uint32_t)__cvta_generic_to_shared(dsm) + 127u) & ~127u;

    auto fill = [&](int kb, int stg) {
        uint32_t ab = sbase + stg * STGB;
        uint32_t bbs = ab + ATSZ;
        const __half* Ak = A + (size_t)m0 * lda + kb * BK;
        const __half* Bk = B + (size_t)n0 * ldb + kb * BK;
        #pragma unroll
        for (int i = 0; i < 4; i++) {
            int q = t + i * 256;
            int r = q >> 3, c = q & 7;
            cpasync16(ab + r * RSTR + c * 16, Ak + (size_t)r * lda + c * 8);
        }
        #pragma unroll
        for (int i = 0; i < 4; i++) {
            int q = t + i * 256;
            int r = q >> 3, c = q & 7;
            cpasync16(bbs + r * RSTR + c * 16, Bk + (size_t)r * ldb + c * 8);
        }
    };

    uint32_t a_off = (uint32_t)((wm * 64 + (lane & 15)) * RSTR + (lane >> 4) * 16);
    uint32_t b_off = (uint32_t)(ATSZ + (wn * 32 + (lane & 7) + ((lane >> 4) << 3)) * RSTR
                                + (((lane >> 3) & 1) * 16));

    float acc[4][4][4];
    #pragma unroll
    for (int i = 0; i < 4; i++)
        #pragma unroll
        for (int j = 0; j < 4; j++)
            #pragma unroll
            for (int r = 0; r < 4; r++) acc[i][j][r] = 0.f;

    const int nk = K / BK;
    fill(0, 0); cp_commit();
    fill(1, 1); cp_commit();

    int st_cur = 0, st_nxt = 2;
    for (int kb = 0; kb < nk; kb++) {
        asm volatile("cp.async.wait_group 1;\n" ::: "memory");  // group kb done
        __syncthreads();

        if (kb + 2 < nk) fill(kb + 2, st_nxt);
        cp_commit();

        uint32_t abase = sbase + st_cur * STGB + a_off;
        uint32_t bbase = sbase + st_cur * STGB + b_off;

        #pragma unroll
        for (int kk = 0; kk < 4; kk++) {
            uint32_t af[4][4];
            #pragma unroll
            for (int mt = 0; mt < 4; mt++)
                ldmx4(af[mt], abase + mt * (16 * RSTR) + kk * 32);
            uint32_t bf[2][4];
            #pragma unroll
            for (int j = 0; j < 2; j++)
                ldmx4(bf[j], bbase + j * (16 * RSTR) + kk * 32);
            #pragma unroll
            for (int mt = 0; mt < 4; mt++)
                #pragma unroll
                for (int nt = 0; nt < 4; nt++)
                    mma_f16(acc[mt][nt], af[mt], &bf[nt >> 1][(nt & 1) * 2]);
        }
        st_cur = (st_cur == NSTAGE - 1) ? 0 : st_cur + 1;
        st_nxt = (st_nxt == NSTAGE - 1) ? 0 : st_nxt + 1;
    }

    // ---- epilogue ----
    #pragma unroll
    for (int mt = 0; mt < 4; mt++) {
        int mA = m0 + wm * 64 + mt * 16 + gr;
        int mB = mA + 8;
        float bA = 0.f, bB = 0.f;
        if (EPI == 1 || EPI == 4) { bA = aux[mA]; bB = aux[mB]; }
        if (EPI == 3) { bA = aux[(size_t)bz * NSP + mA]; bB = aux[(size_t)bz * NSP + mB]; }
        float rsA = 0.f, rsB = 0.f;
        #pragma unroll
        for (int nt = 0; nt < 4; nt++) {
            int n = n0 + wn * 32 + nt * 8 + 2 * gc;
            float v0 = acc[mt][nt][0], v1 = acc[mt][nt][1];
            float v2 = acc[mt][nt][2], v3 = acc[mt][nt][3];
            if (EPI == 0) {
                float c0 = aux[n], c1 = aux[n + 1];
                v0 += c0; v1 += c1; v2 += c0; v3 += c1;
            }
            if (EPI == 1) { v0 += bA; v1 += bA; v2 += bB; v3 += bB; }
            if (EPI == 2) {
                v0 = __expf(v0 * scale); v1 = __expf(v1 * scale);
                v2 = __expf(v2 * scale); v3 = __expf(v3 * scale);
                rsA += v0 + v1; rsB += v2 + v3;
            }
            if (EPI == 3) { v0 *= bA; v1 *= bA; v2 *= bB; v3 *= bB; }
            if (EPI == 4) {
                const float* rp = resid + sC * (size_t)bz;
                float2 r0 = *reinterpret_cast<const float2*>(&rp[(size_t)mA * ldc + n]);
                float2 r1 = *reinterpret_cast<const float2*>(&rp[(size_t)mB * ldc + n]);
                v0 += bA + r0.x; v1 += bA + r0.y; v2 += bB + r1.x; v3 += bB + r1.y;
            }
            if (EPI == 4) {
                float* C = (float*)Cv + sC * (size_t)bz;
                *reinterpret_cast<float2*>(&C[(size_t)mA * ldc + n]) = make_float2(v0, v1);
                *reinterpret_cast<float2*>(&C[(size_t)mB * ldc + n]) = make_float2(v2, v3);
            } else {
                __half* C = (__half*)Cv + sC * (size_t)bz;
                *reinterpret_cast<__half2*>(&C[(size_t)mA * ldc + n]) = __floats2half2_rn(v0, v1);
                *reinterpret_cast<__half2*>(&C[(size_t)mB * ldc + n]) = __floats2half2_rn(v2, v3);
            }
        }
        if (EPI == 2) {
            rsA += __shfl_xor_sync(0xffffffffu, rsA, 1);
            rsA += __shfl_xor_sync(0xffffffffu, rsA, 2);
            rsB += __shfl_xor_sync(0xffffffffu, rsB, 1);
            rsB += __shfl_xor_sync(0xffffffffu, rsB, 2);
            if (gc == 0) {
                sm_rs[wn][wm * 64 + mt * 16 + gr]     = rsA;
                sm_rs[wn][wm * 64 + mt * 16 + gr + 8] = rsB;
            }
        }
    }
    if (EPI == 2) {
        __syncthreads();
        if (t < BM)
            rsp[((size_t)bz * NSP + m0 + t) * 32 + blockIdx.x] =
                sm_rs[0][t] + sm_rs[1][t] + sm_rs[2][t] + sm_rs[3][t];
    }
}

// ---------------- rowsum partial reduce -> 1/sum ----------------
__global__ void __launch_bounds__(256)
rsred_kernel(const float* __restrict__ rsp, float* __restrict__ inv) {
    int row = blockIdx.x * 8 + (threadIdx.x >> 5);
    int lane = threadIdx.x & 31;
    float s = rsp[(size_t)row * 32 + lane];
    #pragma unroll
    for (int o = 16; o; o >>= 1) s += __shfl_xor_sync(0xffffffffu, s, o);
    if (lane == 0) inv[row] = 1.f / s;
}

// ---------------- launcher ----------------
extern "C" void kernel_launch(void* const* d_in, const int* in_sizes, int n_in,
                              void* d_out, int out_size) {
    const float* x    = (const float*)d_in[0];
    const float* gn_w = (const float*)d_in[1];
    const float* gn_b = (const float*)d_in[2];
    const float* wq   = (const float*)d_in[3];
    const float* bq   = (const float*)d_in[4];
    const float* wk   = (const float*)d_in[5];
    const float* bk   = (const float*)d_in[6];
    const float* wv   = (const float*)d_in[7];
    const float* bv   = (const float*)d_in[8];
    const float* wp   = (const float*)d_in[9];
    const float* bp   = (const float*)d_in[10];
    float* out = (float*)d_out;

    __half *hnT, *qkT, *v, *oT, *s, *wqk, *wvh, *wph;
    float *rs, *rsp, *bqk;
    float2 *gnp, *gst;
    cudaGetSymbolAddress((void**)&hnT, g_hnT);
    cudaGetSymbolAddress((void**)&qkT, g_qkT);
    cudaGetSymbolAddress((void**)&v,   g_v);
    cudaGetSymbolAddress((void**)&oT,  g_oT);
    cudaGetSymbolAddress((void**)&s,   g_s);
    cudaGetSymbolAddress((void**)&rs,  g_rs);
    cudaGetSymbolAddress((void**)&rsp, g_rsp);
    cudaGetSymbolAddress((void**)&gnp, g_gnp);
    cudaGetSymbolAddress((void**)&gst, g_gst);
    cudaGetSymbolAddress((void**)&wqk, g_wqk);
    cudaGetSymbolAddress((void**)&bqk, g_bqk);
    cudaGetSymbolAddress((void**)&wvh, g_wv);
    cudaGetSymbolAddress((void**)&wph, g_wp);

    const size_t CN  = (size_t)NSP * CDIM;
    const size_t QKN = (size_t)NSP * 1024;
    const size_t NN  = (size_t)NSP * NSP;
    const float attn_scale = 0.04419417382415922f;  // 1/sqrt(512)
    const int smem = NSTAGE * STGB + 256;           // 110848

    cudaFuncSetAttribute(gemm_h<0>, cudaFuncAttributeMaxDynamicSharedMemorySize, smem);
    cudaFuncSetAttribute(gemm_h<1>, cudaFuncAttributeMaxDynamicSharedMemorySize, smem);
    cudaFuncSetAttribute(gemm_h<2>, cudaFuncAttributeMaxDynamicSharedMemorySize, smem);
    cudaFuncSetAttribute(gemm_h<3>, cudaFuncAttributeMaxDynamicSharedMemorySize, smem);
    cudaFuncSetAttribute(gemm_h<4>, cudaFuncAttributeMaxDynamicSharedMemorySize, smem);

    w2h<<<(CDIM * CDIM + 255) / 256, 256>>>(wq, wk, wv, wp, bq, bk, wqk, wvh, wph, bqk);
    gn_stats1<<<BDIM * GROUPS * 8, 256>>>(x, gnp);
    gn_stats2<<<BDIM * GROUPS, 32>>>(gnp, gst);
    gn_norm<<<BDIM * GROUPS * 8, 256>>>(x, gn_w, gn_b, gst, hnT);

    dim3 blk(256);
    // qkT[n][o] = sum_c hnT[n][c] wqk[o][c] + bqk[o]   M=NSP, N=1024
    gemm_h<0><<<dim3(1024 / BN, NSP / BM, BDIM), blk, smem>>>(
        hnT, wqk, qkT, CDIM, CDIM, CDIM, 1024, CN, 0, QKN, bqk, nullptr, nullptr, 0.f);
    // v[c][n] = sum_k wv[c][k] hnT[n][k] + bv[c]       M=CDIM, N=NSP
    gemm_h<1><<<dim3(NSP / BN, CDIM / BM, BDIM), blk, smem>>>(
        wvh, hnT, v, CDIM, CDIM, CDIM, NSP, 0, CN, CN, bv, nullptr, nullptr, 0.f);
    // s[i][j] = exp(sum_c qT[i][c] kT[j][c] * scale), rowsum partials
    gemm_h<2><<<dim3(NSP / BN, NSP / BM, BDIM), blk, smem>>>(
        qkT, qkT + CDIM, s, CDIM, 1024, 1024, NSP, QKN, QKN, NN,
        nullptr, nullptr, rsp, attn_scale);

    rsred_kernel<<<BDIM * NSP / 8, 256>>>(rsp, rs);

    // oT[i][c] = (sum_j s[i][j] v[c][j]) * rs[b][i]    M=NSP, N=CDIM
    gemm_h<3><<<dim3(CDIM / BN, NSP / BM, BDIM), blk, smem>>>(
        s, v, oT, NSP, NSP, NSP, CDIM, NN, CN, CN, rs, nullptr, nullptr, 0.f);
    // out[o][n] = sum_c wp[o][c] oT[n][c] + bp[o] + x  M=CDIM, N=NSP (fp32)
    gemm_h<4><<<dim3(NSP / BN, CDIM / BM, BDIM), blk, smem>>>(
        wph, oT, out, CDIM, CDIM, CDIM, NSP, 0, CN, CN, bp, x, nullptr, 0.f);
}

// round 16
// speedup vs baseline: 1.0877x; 1.0877x over previous
#include <cuda_runtime.h>
#include <cuda_fp16.h>
#include <cstdint>
#include <math.h>

#define BDIM 2
#define CDIM 512
#define NSP  4096
#define GROUPS 32
#define CPG  16

// ---- static scratch ----
__device__ __half g_hnT[(size_t)BDIM * NSP * CDIM];   // [b][n][c]
__device__ __half g_qkT[(size_t)BDIM * NSP * 1024];   // [b][n][q:512|k:512]
__device__ __half g_v  [(size_t)BDIM * CDIM * NSP];   // [b][c][n]
__device__ __half g_oT [(size_t)BDIM * NSP * CDIM];   // [b][n][c]
__device__ __half g_s  [(size_t)BDIM * NSP * NSP];    // [b][i][j] exp-scores
__device__ float  g_rsp[(size_t)BDIM * NSP * 32];     // row-sum partials [row][jb]
__device__ float  g_rs [(size_t)BDIM * NSP];          // 1/rowsum
__device__ float2 g_gnp[BDIM * GROUPS * 8];           // gn partial (sum, sumsq)
__device__ float2 g_gst[BDIM * GROUPS];               // gn (mean, rstd)
__device__ __half g_wqk[1024 * CDIM];
__device__ float  g_bqk[1024];
__device__ __half g_wv [CDIM * CDIM];
__device__ __half g_wp [CDIM * CDIM];

// ---------------- reductions ----------------
__device__ __forceinline__ float blockReduceSum(float v, float* sh) {
    #pragma unroll
    for (int o = 16; o; o >>= 1) v += __shfl_down_sync(0xffffffffu, v, o);
    int lane = threadIdx.x & 31, wid = threadIdx.x >> 5;
    if (lane == 0) sh[wid] = v;
    __syncthreads();
    int nw = blockDim.x >> 5;
    v = (threadIdx.x < nw) ? sh[threadIdx.x] : 0.f;
    if (wid == 0) {
        #pragma unroll
        for (int o = 16; o; o >>= 1) v += __shfl_down_sync(0xffffffffu, v, o);
    }
    return v;
}

// ---------------- weights fp32->fp16 (+ q|k concat) ----------------
__global__ void __launch_bounds__(256)
w2h(const float* __restrict__ wq, const float* __restrict__ wk,
    const float* __restrict__ wv, const float* __restrict__ wp,
    const float* __restrict__ bq, const float* __restrict__ bk,
    __half* __restrict__ Wqk, __half* __restrict__ Wv,
    __half* __restrict__ Wp, float* __restrict__ Bqk) {
    int i = blockIdx.x * 256 + threadIdx.x;
    if (i < CDIM * CDIM) {
        Wqk[i] = __float2half_rn(wq[i]);
        Wqk[i + CDIM * CDIM] = __float2half_rn(wk[i]);
        Wv[i] = __float2half_rn(wv[i]);
        Wp[i] = __float2half_rn(wp[i]);
    }
    if (i < CDIM) { Bqk[i] = bq[i]; Bqk[i + CDIM] = bk[i]; }
}

// ---------------- GroupNorm pass 1: partial sums ----------------
__global__ void __launch_bounds__(256)
gn_stats1(const float* __restrict__ x, float2* __restrict__ gnp) {
    __shared__ float sh[32];
    int blk = blockIdx.x;
    int chunk = blk & 7, bg = blk >> 3;
    const float* xp = x + (size_t)bg * CPG * NSP + chunk * 512;
    const float4* xp4 = reinterpret_cast<const float4*>(xp);
    int t = threadIdx.x;
    float s = 0.f, ss = 0.f;
    for (int i = t; i < 2048; i += 256) {
        int c = i >> 7, n4 = i & 127;
        float4 v = xp4[c * (NSP / 4) + n4];
        s  += v.x + v.y + v.z + v.w;
        ss += v.x * v.x + v.y * v.y + v.z * v.z + v.w * v.w;
    }
    float ts = blockReduceSum(s, sh);
    __syncthreads();
    float tss = blockReduceSum(ss, sh);
    if (t == 0) gnp[blk] = make_float2(ts, tss);
}

// ---------------- GroupNorm pass 2: reduce to (mean, rstd) ----------------
__global__ void __launch_bounds__(32)
gn_stats2(const float2* __restrict__ gnp, float2* __restrict__ gst) {
    int lane = threadIdx.x;
    float s = 0.f, ss = 0.f;
    if (lane < 8) {
        float2 p = gnp[blockIdx.x * 8 + lane];
        s = p.x; ss = p.y;
    }
    #pragma unroll
    for (int o = 4; o; o >>= 1) {
        s  += __shfl_down_sync(0xffffffffu, s, o);
        ss += __shfl_down_sync(0xffffffffu, ss, o);
    }
    if (lane == 0) {
        float mean = s / 65536.f;
        float var  = ss / 65536.f - mean * mean;
        gst[blockIdx.x] = make_float2(mean, rsqrtf(var + 1e-6f));
    }
}

// ---------------- GroupNorm pass 3: normalize + transpose ----------------
__global__ void __launch_bounds__(256)
gn_norm(const float* __restrict__ x, const float* __restrict__ w,
        const float* __restrict__ bb, const float2* __restrict__ gst,
        __half* __restrict__ hnT) {
    __shared__ float tile[16][129];
    int blk = blockIdx.x;
    int chunk = blk & 7, bg = blk >> 3;
    int b = bg / GROUPS, g = bg % GROUPS;
    const float* xp = x + (size_t)bg * CPG * NSP;
    float2 st = gst[bg];
    float mean = st.x, rstd = st.y;
    int t = threadIdx.x;

    __half* hT = hnT + (size_t)b * NSP * CDIM;

    for (int sub = 0; sub < 4; sub++) {
        int n0 = chunk * 512 + sub * 128;
        #pragma unroll
        for (int e = 0; e < 8; e++) {
            int idx = e * 256 + t;
            int c = idx >> 7, n = idx & 127;
            float v = xp[(size_t)c * NSP + n0 + n];
            tile[c][n] = (v - mean) * rstd * w[g * CPG + c] + bb[g * CPG + c];
        }
        __syncthreads();
        int n = t >> 1, ch = (t & 1) * 8;
        __half2 h0 = __floats2half2_rn(tile[ch + 0][n], tile[ch + 1][n]);
        __half2 h1 = __floats2half2_rn(tile[ch + 2][n], tile[ch + 3][n]);
        __half2 h2 = __floats2half2_rn(tile[ch + 4][n], tile[ch + 5][n]);
        __half2 h3 = __floats2half2_rn(tile[ch + 6][n], tile[ch + 7][n]);
        uint4 pk;
        pk.x = *reinterpret_cast<uint32_t*>(&h0);
        pk.y = *reinterpret_cast<uint32_t*>(&h1);
        pk.z = *reinterpret_cast<uint32_t*>(&h2);
        pk.w = *reinterpret_cast<uint32_t*>(&h3);
        *reinterpret_cast<uint4*>(&hT[(size_t)(n0 + n) * CDIM + g * CPG + ch]) = pk;
        __syncthreads();
    }
}

// ---------------- fp16 tensor-core GEMM body (R13 loop: 2-stage, mid-block fill) ----------------
__device__ __forceinline__ void mma_f16(float* c, const uint32_t* a, const uint32_t* b) {
    asm volatile(
        "mma.sync.aligned.m16n8k16.row.col.f32.f16.f16.f32 "
        "{%0,%1,%2,%3}, {%4,%5,%6,%7}, {%8,%9}, {%0,%1,%2,%3};"
        : "+f"(c[0]), "+f"(c[1]), "+f"(c[2]), "+f"(c[3])
        : "r"(a[0]), "r"(a[1]), "r"(a[2]), "r"(a[3]), "r"(b[0]), "r"(b[1]));
}
__device__ __forceinline__ void ldmx4(uint32_t* r, uint32_t addr) {
    asm volatile("ldmatrix.sync.aligned.m8n8.x4.shared.b16 {%0,%1,%2,%3}, [%4];"
                 : "=r"(r[0]), "=r"(r[1]), "=r"(r[2]), "=r"(r[3]) : "r"(addr));
}
__device__ __forceinline__ void cpasync16(uint32_t dst, const void* src) {
    asm volatile("cp.async.cg.shared.global [%0], [%1], 16;\n" :: "r"(dst), "l"(src));
}
__device__ __forceinline__ void cp_commit() {
    asm volatile("cp.async.commit_group;\n" ::: "memory");
}

// D[m][n] = sum_k A[m][k]*B[n][k]  (fp16, K-contiguous rows)
// EPI: 0:+aux[n] fp16  1:+aux[m] fp16  2:exp(v*scale)+rowsum partials fp16
//      3:*aux[bz*NSP+m] fp16  4:+aux[m]+resid fp32
#define BM 128
#define BN 128
#define BK 64
#define RSTR 144
#define ATSZ (128 * RSTR)        // 18432
#define BTSZ (128 * RSTR)        // 18432
#define STGB (ATSZ + BTSZ)       // 36864
#define NSTAGE 2

template<int EPI>
__device__ __forceinline__ void gemm_body(
    const __half* __restrict__ A, const __half* __restrict__ B, void* __restrict__ Cv,
    int K, int lda, int ldb, int ldc, size_t sA, size_t sB, size_t sC,
    const float* __restrict__ aux, const float* __restrict__ resid,
    float* __restrict__ rsp, float scale,
    int bxi, int byi, int bz, char* dsm, float (*sm_rs)[BM]) {
    A += sA * (size_t)bz;
    B += sB * (size_t)bz;

    const int m0 = byi * BM;
    const int n0 = bxi * BN;
    int t = threadIdx.x, wid = t >> 5, lane = t & 31;
    int wm = wid >> 2, wn = wid & 3;     // 2 x 4 warps; warp tile 64x32
    int gr = lane >> 2, gc = lane & 3;

    uint32_t sbase = ((uint32_t)__cvta_generic_to_shared(dsm) + 127u) & ~127u;

    auto fill = [&](int kb, int stg) {
        uint32_t ab = sbase + stg * STGB;
        uint32_t bbs = ab + ATSZ;
        const __half* Ak = A + (size_t)m0 * lda + kb * BK;
        const __half* Bk = B + (size_t)n0 * ldb + kb * BK;
        #pragma unroll
        for (int i = 0; i < 4; i++) {
            int q = t + i * 256;
            int r = q >> 3, c = q & 7;
            cpasync16(ab + r * RSTR + c * 16, Ak + (size_t)r * lda + c * 8);
        }
        #pragma unroll
        for (int i = 0; i < 4; i++) {
            int q = t + i * 256;
            int r = q >> 3, c = q & 7;
            cpasync16(bbs + r * RSTR + c * 16, Bk + (size_t)r * ldb + c * 8);
        }
    };

    uint32_t a_off = (uint32_t)((wm * 64 + (lane & 15)) * RSTR + (lane >> 4) * 16);
    uint32_t b_off = (uint32_t)(ATSZ + (wn * 32 + (lane & 7) + ((lane >> 4) << 3)) * RSTR
                                + (((lane >> 3) & 1) * 16));

    float acc[4][4][4];
    #pragma unroll
    for (int i = 0; i < 4; i++)
        #pragma unroll
        for (int j = 0; j < 4; j++)
            #pragma unroll
            for (int r = 0; r < 4; r++) acc[i][j][r] = 0.f;

    const int nk = K / BK;
    fill(0, 0); cp_commit();

    for (int kb = 0; kb < nk; kb++) {
        asm volatile("cp.async.wait_group 0;\n" ::: "memory");
        __syncthreads();

        uint32_t abase = sbase + (kb & 1) * STGB + a_off;
        uint32_t bbase = sbase + (kb & 1) * STGB + b_off;

        #pragma unroll
        for (int kk = 0; kk < 4; kk++) {
            uint32_t af[4][4];
            #pragma unroll
            for (int mt = 0; mt < 4; mt++)
                ldmx4(af[mt], abase + mt * (16 * RSTR) + kk * 32);
            uint32_t bf[2][4];
            #pragma unroll
            for (int j = 0; j < 2; j++)
                ldmx4(bf[j], bbase + j * (16 * RSTR) + kk * 32);
            #pragma unroll
            for (int mt = 0; mt < 4; mt++)
                #pragma unroll
                for (int nt = 0; nt < 4; nt++)
                    mma_f16(acc[mt][nt], af[mt], &bf[nt >> 1][(nt & 1) * 2]);
            if (kk == 0) {                   // mid-block prefetch of next stage
                if (kb + 1 < nk) fill(kb + 1, (kb + 1) & 1);
                cp_commit();
            }
        }
    }

    // ---- epilogue ----
    #pragma unroll
    for (int mt = 0; mt < 4; mt++) {
        int mA = m0 + wm * 64 + mt * 16 + gr;
        int mB = mA + 8;
        float bA = 0.f, bB = 0.f;
        if (EPI == 1 || EPI == 4) { bA = aux[mA]; bB = aux[mB]; }
        if (EPI == 3) { bA = aux[(size_t)bz * NSP + mA]; bB = aux[(size_t)bz * NSP + mB]; }
        float rsA = 0.f, rsB = 0.f;
        #pragma unroll
        for (int nt = 0; nt < 4; nt++) {
            int n = n0 + wn * 32 + nt * 8 + 2 * gc;
            float v0 = acc[mt][nt][0], v1 = acc[mt][nt][1];
            float v2 = acc[mt][nt][2], v3 = acc[mt][nt][3];
            if (EPI == 0) {
                float c0 = aux[n], c1 = aux[n + 1];
                v0 += c0; v1 += c1; v2 += c0; v3 += c1;
            }
            if (EPI == 1) { v0 += bA; v1 += bA; v2 += bB; v3 += bB; }
            if (EPI == 2) {
                v0 = __expf(v0 * scale); v1 = __expf(v1 * scale);
                v2 = __expf(v2 * scale); v3 = __expf(v3 * scale);
                rsA += v0 + v1; rsB += v2 + v3;
            }
            if (EPI == 3) { v0 *= bA; v1 *= bA; v2 *= bB; v3 *= bB; }
            if (EPI == 4) {
                const float* rp = resid + sC * (size_t)bz;
                float2 r0 = *reinterpret_cast<const float2*>(&rp[(size_t)mA * ldc + n]);
                float2 r1 = *reinterpret_cast<const float2*>(&rp[(size_t)mB * ldc + n]);
                v0 += bA + r0.x; v1 += bA + r0.y; v2 += bB + r1.x; v3 += bB + r1.y;
            }
            if (EPI == 4) {
                float* C = (float*)Cv + sC * (size_t)bz;
                *reinterpret_cast<float2*>(&C[(size_t)mA * ldc + n]) = make_float2(v0, v1);
                *reinterpret_cast<float2*>(&C[(size_t)mB * ldc + n]) = make_float2(v2, v3);
            } else {
                __half* C = (__half*)Cv + sC * (size_t)bz;
                *reinterpret_cast<__half2*>(&C[(size_t)mA * ldc + n]) = __floats2half2_rn(v0, v1);
                *reinterpret_cast<__half2*>(&C[(size_t)mB * ldc + n]) = __floats2half2_rn(v2, v3);
            }
        }
        if (EPI == 2) {
            rsA += __shfl_xor_sync(0xffffffffu, rsA, 1);
            rsA += __shfl_xor_sync(0xffffffffu, rsA, 2);
            rsB += __shfl_xor_sync(0xffffffffu, rsB, 1);
            rsB += __shfl_xor_sync(0xffffffffu, rsB, 2);
            if (gc == 0) {
                sm_rs[wn][wm * 64 + mt * 16 + gr]     = rsA;
                sm_rs[wn][wm * 64 + mt * 16 + gr + 8] = rsB;
            }
        }
    }
    if (EPI == 2) {
        __syncthreads();
        if (t < BM)
            rsp[((size_t)bz * NSP + m0 + t) * 32 + bxi] =
                sm_rs[0][t] + sm_rs[1][t] + sm_rs[2][t] + sm_rs[3][t];
    }
}

template<int EPI>
__global__ void __launch_bounds__(256, 2)
gemm_h(const __half* __restrict__ A, const __half* __restrict__ B, void* __restrict__ Cv,
       int K, int lda, int ldb, int ldc, size_t sA, size_t sB, size_t sC,
       const float* __restrict__ aux, const float* __restrict__ resid,
       float* __restrict__ rsp, float scale) {
    extern __shared__ char dsm[];
    __shared__ float sm_rs[4][BM];
    gemm_body<EPI>(A, B, Cv, K, lda, ldb, ldc, sA, sB, sC, aux, resid, rsp, scale,
                   blockIdx.x, blockIdx.y, blockIdx.z, dsm, sm_rs);
}

// Fused qk-proj + v-proj: blocks [0,512) -> qk (EPI 0), [512,768) -> v (EPI 1)
__global__ void __launch_bounds__(256, 2)
qkv_fused(const float* __restrict__ bv) {
    extern __shared__ char dsm[];
    __shared__ float sm_rs[4][BM];
    int id = blockIdx.x;
    if (id < 512) {
        // qkT[n][o] = sum_c hnT[n][c] wqk[o][c] + bqk[o]; grid (8, 32, 2)
        gemm_body<0>(g_hnT, g_wqk, g_qkT, CDIM, CDIM, CDIM, 1024,
                     (size_t)NSP * CDIM, 0, (size_t)NSP * 1024,
                     g_bqk, nullptr, nullptr, 0.f,
                     id & 7, (id >> 3) & 31, id >> 8, dsm, sm_rs);
    } else {
        // v[c][n] = sum_k wv[c][k] hnT[n][k] + bv[c]; grid (32, 4, 2)
        id -= 512;
        gemm_body<1>(g_wv, g_hnT, g_v, CDIM, CDIM, CDIM, NSP,
                     0, (size_t)NSP * CDIM, (size_t)NSP * CDIM,
                     bv, nullptr, nullptr, 0.f,
                     id & 31, (id >> 5) & 3, id >> 7, dsm, sm_rs);
    }
}

// ---------------- rowsum partial reduce -> 1/sum ----------------
__global__ void __launch_bounds__(256)
rsred_kernel(const float* __restrict__ rsp, float* __restrict__ inv) {
    int row = blockIdx.x * 8 + (threadIdx.x >> 5);
    int lane = threadIdx.x & 31;
    float s = rsp[(size_t)row * 32 + lane];
    #pragma unroll
    for (int o = 16; o; o >>= 1) s += __shfl_xor_sync(0xffffffffu, s, o);
    if (lane == 0) inv[row] = 1.f / s;
}

// ---------------- launcher ----------------
extern "C" void kernel_launch(void* const* d_in, const int* in_sizes, int n_in,
                              void* d_out, int out_size) {
    const float* x    = (const float*)d_in[0];
    const float* gn_w = (const float*)d_in[1];
    const float* gn_b = (const float*)d_in[2];
    const float* wq   = (const float*)d_in[3];
    const float* bq   = (const float*)d_in[4];
    const float* wk   = (const float*)d_in[5];
    const float* bk   = (const float*)d_in[6];
    const float* wv   = (const float*)d_in[7];
    const float* bv   = (const float*)d_in[8];
    const float* wp   = (const float*)d_in[9];
    const float* bp   = (const float*)d_in[10];
    float* out = (float*)d_out;

    __half *hnT, *qkT, *v, *oT, *s, *wqk, *wvh, *wph;
    float *rs, *rsp, *bqk;
    float2 *gnp, *gst;
    cudaGetSymbolAddress((void**)&hnT, g_hnT);
    cudaGetSymbolAddress((void**)&qkT, g_qkT);
    cudaGetSymbolAddress((void**)&v,   g_v);
    cudaGetSymbolAddress((void**)&oT,  g_oT);
    cudaGetSymbolAddress((void**)&s,   g_s);
    cudaGetSymbolAddress((void**)&rs,  g_rs);
    cudaGetSymbolAddress((void**)&rsp, g_rsp);
    cudaGetSymbolAddress((void**)&gnp, g_gnp);
    cudaGetSymbolAddress((void**)&gst, g_gst);
    cudaGetSymbolAddress((void**)&wqk, g_wqk);
    cudaGetSymbolAddress((void**)&bqk, g_bqk);
    cudaGetSymbolAddress((void**)&wvh, g_wv);
    cudaGetSymbolAddress((void**)&wph, g_wp);

    const size_t CN  = (size_t)NSP * CDIM;
    const size_t NN  = (size_t)NSP * NSP;
    const float attn_scale = 0.04419417382415922f;  // 1/sqrt(512)
    const int smem = NSTAGE * STGB + 256;           // 73984

    cudaFuncSetAttribute(gemm_h<2>, cudaFuncAttributeMaxDynamicSharedMemorySize, smem);
    cudaFuncSetAttribute(gemm_h<3>, cudaFuncAttributeMaxDynamicSharedMemorySize, smem);
    cudaFuncSetAttribute(gemm_h<4>, cudaFuncAttributeMaxDynamicSharedMemorySize, smem);
    cudaFuncSetAttribute(qkv_fused, cudaFuncAttributeMaxDynamicSharedMemorySize, smem);

    w2h<<<(CDIM * CDIM + 255) / 256, 256>>>(wq, wk, wv, wp, bq, bk, wqk, wvh, wph, bqk);
    gn_stats1<<<BDIM * GROUPS * 8, 256>>>(x, gnp);
    gn_stats2<<<BDIM * GROUPS, 32>>>(gnp, gst);
    gn_norm<<<BDIM * GROUPS * 8, 256>>>(x, gn_w, gn_b, gst, hnT);

    dim3 blk(256);
    // fused qk-proj (512 CTAs) + v-proj (256 CTAs)
    qkv_fused<<<768, blk, smem>>>(bv);

    // s[i][j] = exp(sum_c qT[i][c] kT[j][c] * scale), rowsum partials
    gemm_h<2><<<dim3(NSP / BN, NSP / BM, BDIM), blk, smem>>>(
        qkT, qkT + CDIM, s, CDIM, 1024, 1024, NSP, (size_t)NSP * 1024,
        (size_t)NSP * 1024, NN, nullptr, nullptr, rsp, attn_scale);

    rsred_kernel<<<BDIM * NSP / 8, 256>>>(rsp, rs);

    // oT[i][c] = (sum_j s[i][j] v[c][j]) * rs[b][i]    M=NSP, N=CDIM
    gemm_h<3><<<dim3(CDIM / BN, NSP / BM, BDIM), blk, smem>>>(
        s, v, oT, NSP, NSP, NSP, CDIM, NN, CN, CN, rs, nullptr, nullptr, 0.f);
    // out[o][n] = sum_c wp[o][c] oT[n][c] + bp[o] + x  M=CDIM, N=NSP (fp32)
    gemm_h<4><<<dim3(NSP / BN, CDIM / BM, BDIM), blk, smem>>>(
        wph, oT, out, CDIM, CDIM, CDIM, NSP, 0, CN, CN, bp, x, nullptr, 0.f);
}

// round 17
// speedup vs baseline: 1.0969x; 1.0085x over previous
#include <cuda_runtime.h>
#include <cuda_fp16.h>
#include <cstdint>
#include <math.h>

#define BDIM 2
#define CDIM 512
#define NSP  4096
#define GROUPS 32
#define CPG  16

// ---- static scratch ----
__device__ __half g_hnT[(size_t)BDIM * NSP * CDIM];   // [b][n][c]
__device__ __half g_qkT[(size_t)BDIM * NSP * 1024];   // [b][n][q:512|k:512]
__device__ __half g_v  [(size_t)BDIM * CDIM * NSP];   // [b][c][n]
__device__ __half g_oT [(size_t)BDIM * NSP * CDIM];   // [b][n][c]
__device__ __half g_s  [(size_t)BDIM * NSP * NSP];    // [b][i][j] exp-scores
__device__ float  g_rsp[(size_t)BDIM * NSP * 32];     // row-sum partials [row][jb]
__device__ float2 g_gnp[BDIM * GROUPS * 8];           // gn partial (sum, sumsq)
__device__ __half g_wqk[1024 * CDIM];
__device__ float  g_bqk[1024];
__device__ __half g_wv [CDIM * CDIM];
__device__ __half g_wp [CDIM * CDIM];

// ---------------- reductions ----------------
__device__ __forceinline__ float blockReduceSum(float v, float* sh) {
    #pragma unroll
    for (int o = 16; o; o >>= 1) v += __shfl_down_sync(0xffffffffu, v, o);
    int lane = threadIdx.x & 31, wid = threadIdx.x >> 5;
    if (lane == 0) sh[wid] = v;
    __syncthreads();
    int nw = blockDim.x >> 5;
    v = (threadIdx.x < nw) ? sh[threadIdx.x] : 0.f;
    if (wid == 0) {
        #pragma unroll
        for (int o = 16; o; o >>= 1) v += __shfl_down_sync(0xffffffffu, v, o);
    }
    return v;
}

// ---------------- fused: gn partial stats (blocks 0-511) + weight cvt (512-1535) ----------------
__global__ void __launch_bounds__(256)
pre_fused(const float* __restrict__ x, float2* __restrict__ gnp,
          const float* __restrict__ wq, const float* __restrict__ wk,
          const float* __restrict__ wv, const float* __restrict__ wp,
          const float* __restrict__ bq, const float* __restrict__ bk,
          __half* __restrict__ Wqk, __half* __restrict__ Wv,
          __half* __restrict__ Wp, float* __restrict__ Bqk) {
    int id = blockIdx.x;
    if (id < 512) {
        __shared__ float sh[32];
        int chunk = id & 7, bg = id >> 3;
        const float* xp = x + (size_t)bg * CPG * NSP + chunk * 512;
        const float4* xp4 = reinterpret_cast<const float4*>(xp);
        int t = threadIdx.x;
        float s = 0.f, ss = 0.f;
        for (int i = t; i < 2048; i += 256) {
            int c = i >> 7, n4 = i & 127;
            float4 v = xp4[c * (NSP / 4) + n4];
            s  += v.x + v.y + v.z + v.w;
            ss += v.x * v.x + v.y * v.y + v.z * v.z + v.w * v.w;
        }
        float ts = blockReduceSum(s, sh);
        __syncthreads();
        float tss = blockReduceSum(ss, sh);
        if (t == 0) gnp[id] = make_float2(ts, tss);
    } else {
        int i = (id - 512) * 256 + threadIdx.x;
        if (i < CDIM * CDIM) {
            Wqk[i] = __float2half_rn(wq[i]);
            Wqk[i + CDIM * CDIM] = __float2half_rn(wk[i]);
            Wv[i] = __float2half_rn(wv[i]);
            Wp[i] = __float2half_rn(wp[i]);
        }
        if (i < CDIM) { Bqk[i] = bq[i]; Bqk[i + CDIM] = bk[i]; }
    }
}

// ---------------- GroupNorm: local stats reduce + normalize + transpose ----------------
__global__ void __launch_bounds__(256)
gn_norm(const float* __restrict__ x, const float* __restrict__ w,
        const float* __restrict__ bb, const float2* __restrict__ gnp,
        __half* __restrict__ hnT) {
    __shared__ float tile[16][129];
    __shared__ float2 s_st;
    int blk = blockIdx.x;
    int chunk = blk & 7, bg = blk >> 3;
    int b = bg / GROUPS, g = bg % GROUPS;
    const float* xp = x + (size_t)bg * CPG * NSP;
    int t = threadIdx.x;

    if (t == 0) {
        float s = 0.f, ss = 0.f;
        #pragma unroll
        for (int j = 0; j < 8; j++) {
            float2 p = gnp[bg * 8 + j];
            s += p.x; ss += p.y;
        }
        float mean = s / 65536.f;
        float var  = ss / 65536.f - mean * mean;
        s_st = make_float2(mean, rsqrtf(var + 1e-6f));
    }
    __syncthreads();
    float mean = s_st.x, rstd = s_st.y;

    __half* hT = hnT + (size_t)b * NSP * CDIM;

    for (int sub = 0; sub < 4; sub++) {
        int n0 = chunk * 512 + sub * 128;
        #pragma unroll
        for (int e = 0; e < 8; e++) {
            int idx = e * 256 + t;
            int c = idx >> 7, n = idx & 127;
            float v = xp[(size_t)c * NSP + n0 + n];
            tile[c][n] = (v - mean) * rstd * w[g * CPG + c] + bb[g * CPG + c];
        }
        __syncthreads();
        int n = t >> 1, ch = (t & 1) * 8;
        __half2 h0 = __floats2half2_rn(tile[ch + 0][n], tile[ch + 1][n]);
        __half2 h1 = __floats2half2_rn(tile[ch + 2][n], tile[ch + 3][n]);
        __half2 h2 = __floats2half2_rn(tile[ch + 4][n], tile[ch + 5][n]);
        __half2 h3 = __floats2half2_rn(tile[ch + 6][n], tile[ch + 7][n]);
        uint4 pk;
        pk.x = *reinterpret_cast<uint32_t*>(&h0);
        pk.y = *reinterpret_cast<uint32_t*>(&h1);
        pk.z = *reinterpret_cast<uint32_t*>(&h2);
        pk.w = *reinterpret_cast<uint32_t*>(&h3);
        *reinterpret_cast<uint4*>(&hT[(size_t)(n0 + n) * CDIM + g * CPG + ch]) = pk;
        __syncthreads();
    }
}

// ---------------- fp16 tensor-core GEMM body (2-stage, mid-block fill) ----------------
__device__ __forceinline__ void mma_f16(float* c, const uint32_t* a, const uint32_t* b) {
    asm volatile(
        "mma.sync.aligned.m16n8k16.row.col.f32.f16.f16.f32 "
        "{%0,%1,%2,%3}, {%4,%5,%6,%7}, {%8,%9}, {%0,%1,%2,%3};"
        : "+f"(c[0]), "+f"(c[1]), "+f"(c[2]), "+f"(c[3])
        : "r"(a[0]), "r"(a[1]), "r"(a[2]), "r"(a[3]), "r"(b[0]), "r"(b[1]));
}
__device__ __forceinline__ void ldmx4(uint32_t* r, uint32_t addr) {
    asm volatile("ldmatrix.sync.aligned.m8n8.x4.shared.b16 {%0,%1,%2,%3}, [%4];"
                 : "=r"(r[0]), "=r"(r[1]), "=r"(r[2]), "=r"(r[3]) : "r"(addr));
}
__device__ __forceinline__ void cpasync16(uint32_t dst, const void* src) {
    asm volatile("cp.async.cg.shared.global [%0], [%1], 16;\n" :: "r"(dst), "l"(src));
}
__device__ __forceinline__ void cp_commit() {
    asm volatile("cp.async.commit_group;\n" ::: "memory");
}

// D[m][n] = sum_k A[m][k]*B[n][k]  (fp16, K-contiguous rows)
// EPI: 0:+aux[n] fp16  1:+aux[m] fp16  2:exp(v*scale)+rowsum partials fp16
//      3:*(1/rowsum from aux=rsp partials) fp16  4:+aux[m]+resid fp32
#define BM 128
#define BN 128
#define BK 64
#define RSTR 144
#define ATSZ (128 * RSTR)        // 18432
#define BTSZ (128 * RSTR)        // 18432
#define STGB (ATSZ + BTSZ)       // 36864
#define NSTAGE 2

template<int EPI>
__device__ __forceinline__ void gemm_body(
    const __half* __restrict__ A, const __half* __restrict__ B, void* __restrict__ Cv,
    int K, int lda, int ldb, int ldc, size_t sA, size_t sB, size_t sC,
    const float* __restrict__ aux, const float* __restrict__ resid,
    float* __restrict__ rsp, float scale,
    int bxi, int byi, int bz, char* dsm, float (*sm_rs)[BM]) {
    A += sA * (size_t)bz;
    B += sB * (size_t)bz;

    const int m0 = byi * BM;
    const int n0 = bxi * BN;
    int t = threadIdx.x, wid = t >> 5, lane = t & 31;
    int wm = wid >> 2, wn = wid & 3;     // 2 x 4 warps; warp tile 64x32
    int gr = lane >> 2, gc = lane & 3;

    uint32_t sbase = ((uint32_t)__cvta_generic_to_shared(dsm) + 127u) & ~127u;

    auto fill = [&](int kb, int stg) {
        uint32_t ab = sbase + stg * STGB;
        uint32_t bbs = ab + ATSZ;
        const __half* Ak = A + (size_t)m0 * lda + kb * BK;
        const __half* Bk = B + (size_t)n0 * ldb + kb * BK;
        #pragma unroll
        for (int i = 0; i < 4; i++) {
            int q = t + i * 256;
            int r = q >> 3, c = q & 7;
            cpasync16(ab + r * RSTR + c * 16, Ak + (size_t)r * lda + c * 8);
        }
        #pragma unroll
        for (int i = 0; i < 4; i++) {
            int q = t + i * 256;
            int r = q >> 3, c = q & 7;
            cpasync16(bbs + r * RSTR + c * 16, Bk + (size_t)r * ldb + c * 8);
        }
    };

    uint32_t a_off = (uint32_t)((wm * 64 + (lane & 15)) * RSTR + (lane >> 4) * 16);
    uint32_t b_off = (uint32_t)(ATSZ + (wn * 32 + (lane & 7) + ((lane >> 4) << 3)) * RSTR
                                + (((lane >> 3) & 1) * 16));

    float acc[4][4][4];
    #pragma unroll
    for (int i = 0; i < 4; i++)
        #pragma unroll
        for (int j = 0; j < 4; j++)
            #pragma unroll
            for (int r = 0; r < 4; r++) acc[i][j][r] = 0.f;

    const int nk = K / BK;
    fill(0, 0); cp_commit();

    // EPI==3: reduce rowsum partials for this CTA's 128 rows (overlaps cp.async)
    if (EPI == 3) {
        if (t < BM) {
            const float* p = aux + ((size_t)bz * NSP + m0 + t) * 32;
            float s = 0.f;
            #pragma unroll
            for (int j = 0; j < 32; j++) s += p[j];
            sm_rs[0][t] = 1.f / s;
        }
        __syncthreads();
    }

    for (int kb = 0; kb < nk; kb++) {
        asm volatile("cp.async.wait_group 0;\n" ::: "memory");
        __syncthreads();

        uint32_t abase = sbase + (kb & 1) * STGB + a_off;
        uint32_t bbase = sbase + (kb & 1) * STGB + b_off;

        #pragma unroll
        for (int kk = 0; kk < 4; kk++) {
            uint32_t af[4][4];
            #pragma unroll
            for (int mt = 0; mt < 4; mt++)
                ldmx4(af[mt], abase + mt * (16 * RSTR) + kk * 32);
            uint32_t bf[2][4];
            #pragma unroll
            for (int j = 0; j < 2; j++)
                ldmx4(bf[j], bbase + j * (16 * RSTR) + kk * 32);
            #pragma unroll
            for (int mt = 0; mt < 4; mt++)
                #pragma unroll
                for (int nt = 0; nt < 4; nt++)
                    mma_f16(acc[mt][nt], af[mt], &bf[nt >> 1][(nt & 1) * 2]);
            if (kk == 0) {                   // mid-block prefetch of next stage
                if (kb + 1 < nk) fill(kb + 1, (kb + 1) & 1);
                cp_commit();
            }
        }
    }

    // ---- epilogue ----
    #pragma unroll
    for (int mt = 0; mt < 4; mt++) {
        int mA = m0 + wm * 64 + mt * 16 + gr;
        int mB = mA + 8;
        float bA = 0.f, bB = 0.f;
        if (EPI == 1 || EPI == 4) { bA = aux[mA]; bB = aux[mB]; }
        if (EPI == 3) {
            bA = sm_rs[0][wm * 64 + mt * 16 + gr];
            bB = sm_rs[0][wm * 64 + mt * 16 + gr + 8];
        }
        float rsA = 0.f, rsB = 0.f;
        #pragma unroll
        for (int nt = 0; nt < 4; nt++) {
            int n = n0 + wn * 32 + nt * 8 + 2 * gc;
            float v0 = acc[mt][nt][0], v1 = acc[mt][nt][1];
            float v2 = acc[mt][nt][2], v3 = acc[mt][nt][3];
            if (EPI == 0) {
                float c0 = aux[n], c1 = aux[n + 1];
                v0 += c0; v1 += c1; v2 += c0; v3 += c1;
            }
            if (EPI == 1) { v0 += bA; v1 += bA; v2 += bB; v3 += bB; }
            if (EPI == 2) {
                v0 = __expf(v0 * scale); v1 = __expf(v1 * scale);
                v2 = __expf(v2 * scale); v3 = __expf(v3 * scale);
                rsA += v0 + v1; rsB += v2 + v3;
            }
            if (EPI == 3) { v0 *= bA; v1 *= bA; v2 *= bB; v3 *= bB; }
            if (EPI == 4) {
                const float* rp = resid + sC * (size_t)bz;
                float2 r0 = *reinterpret_cast<const float2*>(&rp[(size_t)mA * ldc + n]);
                float2 r1 = *reinterpret_cast<const float2*>(&rp[(size_t)mB * ldc + n]);
                v0 += bA + r0.x; v1 += bA + r0.y; v2 += bB + r1.x; v3 += bB + r1.y;
            }
            if (EPI == 4) {
                float* C = (float*)Cv + sC * (size_t)bz;
                *reinterpret_cast<float2*>(&C[(size_t)mA * ldc + n]) = make_float2(v0, v1);
                *reinterpret_cast<float2*>(&C[(size_t)mB * ldc + n]) = make_float2(v2, v3);
            } else {
                __half* C = (__half*)Cv + sC * (size_t)bz;
                *reinterpret_cast<__half2*>(&C[(size_t)mA * ldc + n]) = __floats2half2_rn(v0, v1);
                *reinterpret_cast<__half2*>(&C[(size_t)mB * ldc + n]) = __floats2half2_rn(v2, v3);
            }
        }
        if (EPI == 2) {
            rsA += __shfl_xor_sync(0xffffffffu, rsA, 1);
            rsA += __shfl_xor_sync(0xffffffffu, rsA, 2);
            rsB += __shfl_xor_sync(0xffffffffu, rsB, 1);
            rsB += __shfl_xor_sync(0xffffffffu, rsB, 2);
            if (gc == 0) {
                sm_rs[wn][wm * 64 + mt * 16 + gr]     = rsA;
                sm_rs[wn][wm * 64 + mt * 16 + gr + 8] = rsB;
            }
        }
    }
    if (EPI == 2) {
        __syncthreads();
        if (t < BM)
            rsp[((size_t)bz * NSP + m0 + t) * 32 + bxi] =
                sm_rs[0][t] + sm_rs[1][t] + sm_rs[2][t] + sm_rs[3][t];
    }
}

template<int EPI>
__global__ void __launch_bounds__(256, 2)
gemm_h(const __half* __restrict__ A, const __half* __restrict__ B, void* __restrict__ Cv,
       int K, int lda, int ldb, int ldc, size_t sA, size_t sB, size_t sC,
       const float* __restrict__ aux, const float* __restrict__ resid,
       float* __restrict__ rsp, float scale) {
    extern __shared__ char dsm[];
    __shared__ float sm_rs[4][BM];
    gemm_body<EPI>(A, B, Cv, K, lda, ldb, ldc, sA, sB, sC, aux, resid, rsp, scale,
                   blockIdx.x, blockIdx.y, blockIdx.z, dsm, sm_rs);
}

// Fused qk-proj + v-proj: blocks [0,512) -> qk (EPI 0), [512,768) -> v (EPI 1)
__global__ void __launch_bounds__(256, 2)
qkv_fused(const float* __restrict__ bv) {
    extern __shared__ char dsm[];
    __shared__ float sm_rs[4][BM];
    int id = blockIdx.x;
    if (id < 512) {
        gemm_body<0>(g_hnT, g_wqk, g_qkT, CDIM, CDIM, CDIM, 1024,
                     (size_t)NSP * CDIM, 0, (size_t)NSP * 1024,
                     g_bqk, nullptr, nullptr, 0.f,
                     id & 7, (id >> 3) & 31, id >> 8, dsm, sm_rs);
    } else {
        id -= 512;
        gemm_body<1>(g_wv, g_hnT, g_v, CDIM, CDIM, CDIM, NSP,
                     0, (size_t)NSP * CDIM, (size_t)NSP * CDIM,
                     bv, nullptr, nullptr, 0.f,
                     id & 31, (id >> 5) & 3, id >> 7, dsm, sm_rs);
    }
}

// ---------------- launcher ----------------
extern "C" void kernel_launch(void* const* d_in, const int* in_sizes, int n_in,
                              void* d_out, int out_size) {
    const float* x    = (const float*)d_in[0];
    const float* gn_w = (const float*)d_in[1];
    const float* gn_b = (const float*)d_in[2];
    const float* wq   = (const float*)d_in[3];
    const float* bq   = (const float*)d_in[4];
    const float* wk   = (const float*)d_in[5];
    const float* bk   = (const float*)d_in[6];
    const float* wv   = (const float*)d_in[7];
    const float* bv   = (const float*)d_in[8];
    const float* wp   = (const float*)d_in[9];
    const float* bp   = (const float*)d_in[10];
    float* out = (float*)d_out;

    __half *hnT, *qkT, *v, *oT, *s, *wqk, *wvh, *wph;
    float *rsp, *bqk;
    float2 *gnp;
    cudaGetSymbolAddress((void**)&hnT, g_hnT);
    cudaGetSymbolAddress((void**)&qkT, g_qkT);
    cudaGetSymbolAddress((void**)&v,   g_v);
    cudaGetSymbolAddress((void**)&oT,  g_oT);
    cudaGetSymbolAddress((void**)&s,   g_s);
    cudaGetSymbolAddress((void**)&rsp, g_rsp);
    cudaGetSymbolAddress((void**)&gnp, g_gnp);
    cudaGetSymbolAddress((void**)&wqk, g_wqk);
    cudaGetSymbolAddress((void**)&bqk, g_bqk);
    cudaGetSymbolAddress((void**)&wvh, g_wv);
    cudaGetSymbolAddress((void**)&wph, g_wp);

    const size_t CN  = (size_t)NSP * CDIM;
    const size_t NN  = (size_t)NSP * NSP;
    const float attn_scale = 0.04419417382415922f;  // 1/sqrt(512)
    const int smem = NSTAGE * STGB + 256;           // 73984

    cudaFuncSetAttribute(gemm_h<2>, cudaFuncAttributeMaxDynamicSharedMemorySize, smem);
    cudaFuncSetAttribute(gemm_h<3>, cudaFuncAttributeMaxDynamicSharedMemorySize, smem);
    cudaFuncSetAttribute(gemm_h<4>, cudaFuncAttributeMaxDynamicSharedMemorySize, smem);
    cudaFuncSetAttribute(qkv_fused, cudaFuncAttributeMaxDynamicSharedMemorySize, smem);

    // fused: gn partial stats (512) + weight fp16 cvt (1024)
    pre_fused<<<1536, 256>>>(x, gnp, wq, wk, wv, wp, bq, bk, wqk, wvh, wph, bqk);
    // gn: local stats reduce + normalize + transpose
    gn_norm<<<BDIM * GROUPS * 8, 256>>>(x, gn_w, gn_b, gnp, hnT);

    dim3 blk(256);
    // fused qk-proj (512 CTAs) + v-proj (256 CTAs)
    qkv_fused<<<768, blk, smem>>>(bv);

    // s[i][j] = exp(sum_c qT[i][c] kT[j][c] * scale), rowsum partials
    gemm_h<2><<<dim3(NSP / BN, NSP / BM, BDIM), blk, smem>>>(
        qkT, qkT + CDIM, s, CDIM, 1024, 1024, NSP, (size_t)NSP * 1024,
        (size_t)NSP * 1024, NN, nullptr, nullptr, rsp, attn_scale);

    // oT[i][c] = (sum_j s[i][j] v[c][j]) * (1/rowsum[i], computed in prologue)
    gemm_h<3><<<dim3(CDIM / BN, NSP / BM, BDIM), blk, smem>>>(
        s, v, oT, NSP, NSP, NSP, CDIM, NN, CN, CN, rsp, nullptr, nullptr, 0.f);
    // out[o][n] = sum_c wp[o][c] oT[n][c] + bp[o] + x  M=CDIM, N=NSP (fp32)
    gemm_h<4><<<dim3(NSP / BN, CDIM / BM, BDIM), blk, smem>>>(
        wph, oT, out, CDIM, CDIM, CDIM, NSP, 0, CN, CN, bp, x, nullptr, 0.f);
}